// round 16
// baseline (speedup 1.0000x reference)
#include <cuda_runtime.h>
#include <cuda_bf16.h>
#include <math.h>
#include <stdint.h>

#define B_SZ 4096
#define D_SZ 32
#define H_SZ 1024
#define MT   (B_SZ * D_SZ)

// ---------------- scratch ----------------
__device__ float g_h1[B_SZ * H_SZ];
__device__ float g_h2[B_SZ * H_SZ];
__device__ float g_h3[B_SZ * H_SZ];
__device__ float g_W0T[D_SZ * H_SZ];
__device__ __nv_bfloat16 g_U1h[(size_t)MT * H_SZ];
__device__ __nv_bfloat16 g_U2h[(size_t)MT * H_SZ];
__device__ __nv_bfloat16 g_U2l[(size_t)MT * H_SZ];
__device__ __align__(256) uint8_t g_qU1 [(size_t)MT * H_SZ];
__device__ __align__(256) uint8_t g_qU1l[(size_t)MT * H_SZ];
__device__ __align__(256) uint8_t g_qU2 [(size_t)MT * H_SZ];
__device__ __align__(256) uint8_t g_qU2l[(size_t)MT * H_SZ];
__device__ __nv_bfloat16 g_W1h[H_SZ * H_SZ], g_W2h[H_SZ * H_SZ];
__device__ __align__(256) uint8_t g_qW1[H_SZ * H_SZ], g_qW1l[H_SZ * H_SZ];
__device__ __align__(256) uint8_t g_qW2[H_SZ * H_SZ], g_qW2l[H_SZ * H_SZ];
__device__ float g_sU1[MT], g_sU2[MT], g_sW1[H_SZ], g_sW2[H_SZ];
__device__ float g_tpart[8 * B_SZ];

// ---------------- helpers ----------------
__device__ __forceinline__ uint32_t smem_u32_of(const void* p) {
    uint32_t a;
    asm("{ .reg .u64 t; cvta.to.shared.u64 t, %1; cvt.u32.u64 %0, t; }" : "=r"(a) : "l"(p));
    return a;
}
__device__ __forceinline__ void ldsm4(uint32_t r[4], uint32_t addr) {
    asm volatile("ldmatrix.sync.aligned.m8n8.x4.shared.b16 {%0,%1,%2,%3}, [%4];"
                 : "=r"(r[0]), "=r"(r[1]), "=r"(r[2]), "=r"(r[3]) : "r"(addr));
}
__device__ __forceinline__ void mma16816(float c[4], const uint32_t a[4],
                                         uint32_t b0, uint32_t b1) {
    asm volatile("mma.sync.aligned.m16n8k16.row.col.f32.bf16.bf16.f32 "
                 "{%0,%1,%2,%3}, {%4,%5,%6,%7}, {%8,%9}, {%0,%1,%2,%3};"
                 : "+f"(c[0]), "+f"(c[1]), "+f"(c[2]), "+f"(c[3])
                 : "r"(a[0]), "r"(a[1]), "r"(a[2]), "r"(a[3]), "r"(b0), "r"(b1));
}
__device__ __forceinline__ void imma16832(int c[4], const uint32_t a[4],
                                          uint32_t b0, uint32_t b1) {
    asm volatile("mma.sync.aligned.m16n8k32.row.col.s32.s8.s8.s32 "
                 "{%0,%1,%2,%3}, {%4,%5,%6,%7}, {%8,%9}, {%0,%1,%2,%3};"
                 : "+r"(c[0]), "+r"(c[1]), "+r"(c[2]), "+r"(c[3])
                 : "r"(a[0]), "r"(a[1]), "r"(a[2]), "r"(a[3]), "r"(b0), "r"(b1));
}
__device__ __forceinline__ void bsplit2(float x, float y, uint32_t& hi, uint32_t& lo) {
    __nv_bfloat16 hx = __float2bfloat16_rn(x), hy = __float2bfloat16_rn(y);
    __nv_bfloat16 lx = __float2bfloat16_rn(x - __bfloat162float(hx));
    __nv_bfloat16 ly = __float2bfloat16_rn(y - __bfloat162float(hy));
    hi = (uint32_t)__bfloat16_as_ushort(hx) | ((uint32_t)__bfloat16_as_ushort(hy) << 16);
    lo = (uint32_t)__bfloat16_as_ushort(lx) | ((uint32_t)__bfloat16_as_ushort(ly) << 16);
}
__device__ __forceinline__ uint32_t q8x4(float a, float b, float c, float d, float inv) {
    int q0 = max(-127, min(127, __float2int_rn(a * inv)));
    int q1 = max(-127, min(127, __float2int_rn(b * inv)));
    int q2 = max(-127, min(127, __float2int_rn(c * inv)));
    int q3 = max(-127, min(127, __float2int_rn(d * inv)));
    return (uint32_t)(q0 & 255) | ((uint32_t)(q1 & 255) << 8) |
           ((uint32_t)(q2 & 255) << 16) | ((uint32_t)(q3 & 255) << 24);
}
__device__ __forceinline__ void cpa16(uint32_t dst, const void* src) {
    asm volatile("cp.async.cg.shared.global [%0], [%1], 16;" :: "r"(dst), "l"(src));
}
#define CP_COMMIT() asm volatile("cp.async.commit_group;" ::: "memory")
#define CP_WAIT0()  asm volatile("cp.async.wait_group 0;" ::: "memory")
#define CP_WAIT1()  asm volatile("cp.async.wait_group 1;" ::: "memory")

// =====================================================================
// Tangent GEMM: bf16 hi*hi + int8 cross terms, 3-stage cp.async pipeline
// Block 128x128, 8 warps (64x32). smem/stage: Ah,Bh (80B pitch) + 4 int8
// planes (48B pitch) = 45056 B. K=1024 in 32-wide tiles.
// =====================================================================
#define OAHB 0
#define OBHB 10240
#define OQA  20480
#define OQAL 26624
#define OQBL 32768
#define OQBH 38912
#define STG2 45056
#define SMEM_TAN (3 * STG2)

template <int MODE>
__global__ void __launch_bounds__(256, 1)
tan2(const __nv_bfloat16* __restrict__ Ahb, const uint8_t* __restrict__ qAg,
     const uint8_t* __restrict__ qAlg, const float* __restrict__ sAg,
     const __nv_bfloat16* __restrict__ Bhb, const uint8_t* __restrict__ qBg,
     const uint8_t* __restrict__ qBlg, const float* __restrict__ sBg,
     const float* __restrict__ hs, const float* __restrict__ W3p,
     __nv_bfloat16* __restrict__ U2h, __nv_bfloat16* __restrict__ U2l)
{
    extern __shared__ char sm[];
    __shared__ float red[4][4];
    const uint32_t sb = smem_u32_of(sm);
    const int tid = threadIdx.x, lane = tid & 31, wid = tid >> 5;
    const int warpM = wid >> 2, warpN = wid & 3;
    const int wr = warpM * 64, wn = warpN * 32;
    const int rowBase = blockIdx.y * 128, colBase = blockIdx.x * 128;

    float acc[4][4][4];
    int   I[4][4][4];
#pragma unroll
    for (int a = 0; a < 4; a++)
#pragma unroll
        for (int b = 0; b < 4; b++)
#pragma unroll
            for (int c = 0; c < 4; c++) { acc[a][b][c] = 0.0f; I[a][b][c] = 0; }

    const int rA0 = (tid * 2) >> 2,     kA0 = (tid * 2) & 3;
    const int rA1 = (tid * 2 + 1) >> 2, kA1 = (tid * 2 + 1) & 3;
    const int r8 = tid >> 1, k8 = tid & 1;

    auto ISSUE = [&](int kt) {
        const uint32_t s0 = sb + (uint32_t)(kt % 3) * STG2;
        const int kb = kt * 32;
        cpa16(s0 + OAHB + rA0 * 80 + kA0 * 16,
              Ahb + (((size_t)(rowBase + rA0)) << 10) + kb + kA0 * 8);
        cpa16(s0 + OAHB + rA1 * 80 + kA1 * 16,
              Ahb + (((size_t)(rowBase + rA1)) << 10) + kb + kA1 * 8);
        cpa16(s0 + OBHB + rA0 * 80 + kA0 * 16,
              Bhb + (((size_t)(colBase + rA0)) << 10) + kb + kA0 * 8);
        cpa16(s0 + OBHB + rA1 * 80 + kA1 * 16,
              Bhb + (((size_t)(colBase + rA1)) << 10) + kb + kA1 * 8);
        const uint32_t off8 = (uint32_t)(r8 * 48 + k8 * 16);
        const size_t gA = (((size_t)(rowBase + r8)) << 10) + kb + k8 * 16;
        const size_t gB = (((size_t)(colBase + r8)) << 10) + kb + k8 * 16;
        cpa16(s0 + OQA  + off8, qAg  + gA);
        cpa16(s0 + OQAL + off8, qAlg + gA);
        cpa16(s0 + OQBL + off8, qBlg + gB);
        cpa16(s0 + OQBH + off8, qBg  + gB);
        CP_COMMIT();
    };

    ISSUE(0);
    ISSUE(1);

    const int aRow = wr + (lane & 15);
    const int aChk = lane >> 4;
    const int bRowOff = ((lane >> 4) << 3) + (lane & 7);
    const int bChk = (lane >> 3) & 1;

    for (int kt = 0; kt < 32; kt++) {
        if (kt < 31) { CP_WAIT1(); } else { CP_WAIT0(); }
        __syncthreads();
        if (kt + 2 < 32) ISSUE(kt + 2);

        const uint32_t base = sb + (uint32_t)(kt % 3) * STG2;

        // bf16 hi*hi
#pragma unroll
        for (int ks = 0; ks < 2; ks++) {
            uint32_t ah[4][4], bh[2][4];
#pragma unroll
            for (int mi = 0; mi < 4; mi++)
                ldsm4(ah[mi], base + OAHB + (uint32_t)((aRow + mi * 16) * 80 + (aChk + ks * 2) * 16));
#pragma unroll
            for (int pr = 0; pr < 2; pr++)
                ldsm4(bh[pr], base + OBHB + (uint32_t)((wn + pr * 16 + bRowOff) * 80 + (bChk + ks * 2) * 16));
#pragma unroll
            for (int mi = 0; mi < 4; mi++)
#pragma unroll
                for (int ni = 0; ni < 4; ni++) {
                    const int pr = ni >> 1, o = (ni & 1) * 2;
                    mma16816(acc[mi][ni], ah[mi], bh[pr][o], bh[pr][o + 1]);
                }
        }

        // int8 cross terms, one shared int32 accumulator
        {
            uint32_t qa[4][4], qal[4][4], qb[2][4], qbl[2][4];
#pragma unroll
            for (int mi = 0; mi < 4; mi++) {
                uint32_t ad = base + OQA + (uint32_t)((aRow + mi * 16) * 48 + aChk * 16);
                ldsm4(qa[mi], ad);
                ldsm4(qal[mi], ad + (OQAL - OQA));
            }
#pragma unroll
            for (int pr = 0; pr < 2; pr++) {
                uint32_t bd = base + OQBL + (uint32_t)((wn + pr * 16 + bRowOff) * 48 + bChk * 16);
                ldsm4(qbl[pr], bd);
                ldsm4(qb[pr],  bd + (OQBH - OQBL));
            }
#pragma unroll
            for (int mi = 0; mi < 4; mi++)
#pragma unroll
                for (int ni = 0; ni < 4; ni++) {
                    const int pr = ni >> 1, o = (ni & 1) * 2;
                    imma16832(I[mi][ni], qa[mi],  qbl[pr][o], qbl[pr][o + 1]);
                    imma16832(I[mi][ni], qal[mi], qb[pr][o],  qb[pr][o + 1]);
                }
        }
    }

    // fold int32 cross accumulator: acc += (sA*sB/256) * I
    const int l4 = lane >> 2, l2 = (lane & 3) * 2;
    {
        float sa0[4], sa1[4], sb0[4], sb1[4];
#pragma unroll
        for (int mi = 0; mi < 4; mi++) {
            int r = rowBase + wr + mi * 16 + l4;
            sa0[mi] = sAg[r]; sa1[mi] = sAg[r + 8];
        }
#pragma unroll
        for (int ni = 0; ni < 4; ni++) {
            int c = colBase + wn + ni * 8 + l2;
            sb0[ni] = sBg[c]; sb1[ni] = sBg[c + 1];
        }
        const float K8 = 1.0f / 256.0f;
#pragma unroll
        for (int mi = 0; mi < 4; mi++)
#pragma unroll
            for (int ni = 0; ni < 4; ni++) {
                acc[mi][ni][0] += (float)I[mi][ni][0] * (K8 * sa0[mi] * sb0[ni]);
                acc[mi][ni][1] += (float)I[mi][ni][1] * (K8 * sa0[mi] * sb1[ni]);
                acc[mi][ni][2] += (float)I[mi][ni][2] * (K8 * sa1[mi] * sb0[ni]);
                acc[mi][ni][3] += (float)I[mi][ni][3] * (K8 * sa1[mi] * sb1[ni]);
            }
    }

    if (MODE == 1) {
#pragma unroll
        for (int mi = 0; mi < 4; mi++) {
            int r0 = rowBase + wr + mi * 16 + l4;
            int b = r0 >> 5;
#pragma unroll
            for (int ni = 0; ni < 4; ni++) {
                int c = colBase + wn + ni * 8 + l2;
                float2 h = *reinterpret_cast<const float2*>(hs + (size_t)b * H_SZ + c);
                float s0 = 1.0f - h.x * h.x, s1 = 1.0f - h.y * h.y;
                uint32_t hi, lo;
                bsplit2(acc[mi][ni][0] * s0, acc[mi][ni][1] * s1, hi, lo);
                *reinterpret_cast<uint32_t*>(U2h + (size_t)r0 * H_SZ + c) = hi;
                *reinterpret_cast<uint32_t*>(U2l + (size_t)r0 * H_SZ + c) = lo;
                bsplit2(acc[mi][ni][2] * s0, acc[mi][ni][3] * s1, hi, lo);
                *reinterpret_cast<uint32_t*>(U2h + (size_t)(r0 + 8) * H_SZ + c) = hi;
                *reinterpret_cast<uint32_t*>(U2l + (size_t)(r0 + 8) * H_SZ + c) = lo;
            }
        }
    } else {
        float p[2] = {0.0f, 0.0f};
#pragma unroll
        for (int mi = 0; mi < 4; mi++) {
            int r0 = rowBase + wr + mi * 16 + l4;
            int b = r0 >> 5, d0 = r0 & 31;
#pragma unroll
            for (int ni = 0; ni < 4; ni++) {
                int c = colBase + wn + ni * 8 + l2;
                float2 h  = *reinterpret_cast<const float2*>(hs + (size_t)b * H_SZ + c);
                float s0 = 1.0f - h.x * h.x, s1 = 1.0f - h.y * h.y;
                float2 w0 = *reinterpret_cast<const float2*>(W3p + (size_t)d0 * H_SZ + c);
                float2 w1 = *reinterpret_cast<const float2*>(W3p + (size_t)(d0 + 8) * H_SZ + c);
                p[mi >> 1] += acc[mi][ni][0] * s0 * w0.x + acc[mi][ni][1] * s1 * w0.y
                            + acc[mi][ni][2] * s0 * w1.x + acc[mi][ni][3] * s1 * w1.y;
            }
        }
#pragma unroll
        for (int j = 0; j < 2; j++) {
            float v = p[j];
#pragma unroll
            for (int o = 16; o > 0; o >>= 1) v += __shfl_xor_sync(0xffffffffu, v, o);
            if (lane == 0) red[warpM * 2 + j][warpN] = v;
        }
        __syncthreads();
        if (tid < 4) {
            float s = red[tid][0] + red[tid][1] + red[tid][2] + red[tid][3];
            g_tpart[blockIdx.x * B_SZ + (rowBase >> 5) + tid] = s;
        }
    }
}

// =====================================================================
// Forward GEMM (bf16 3-term, inline conversion — unchanged, passing)
// =====================================================================
#define FPLANE 10240
#define FSBUF  (4 * FPLANE)
#define SMEM_FWD (2 * FSBUF)

__global__ void __launch_bounds__(256, 1)
fwd_gemm(const float* __restrict__ A, const float* __restrict__ W,
         const float* __restrict__ bias, float* __restrict__ C)
{
    extern __shared__ char sm[];
    const uint32_t sb = smem_u32_of(sm);
    const int tid = threadIdx.x, lane = tid & 31, wid = tid >> 5;
    const int warpM = wid >> 2, warpN = wid & 3;
    const int wr = warpM * 64, wn = warpN * 32;
    const int rowBase = blockIdx.y * 128, colBase = blockIdx.x * 128;

    float acc[4][4][4];
#pragma unroll
    for (int a = 0; a < 4; a++)
#pragma unroll
        for (int b = 0; b < 4; b++)
#pragma unroll
            for (int c = 0; c < 4; c++) acc[a][b][c] = 0.0f;

    const int aRow = wr + (lane & 15);
    const int aChk = lane >> 4;
    const int bRowOff = ((lane >> 4) << 3) + (lane & 7);
    const int bChk = (lane >> 3) & 1;

    float4 va[4], vb[4];
    auto LDG = [&](int kt) {
        const int kb = kt * 32;
#pragma unroll
        for (int i = 0; i < 4; i++) {
            int q = tid + i * 256;
            int r = q >> 3, kq = q & 7, k0 = kb + kq * 4;
            va[i] = *reinterpret_cast<const float4*>(A + (size_t)(rowBase + r) * H_SZ + k0);
            vb[i] = *reinterpret_cast<const float4*>(W + (size_t)(colBase + r) * H_SZ + k0);
        }
    };
    auto STS = [&](int s) {
#pragma unroll
        for (int i = 0; i < 4; i++) {
            int q = tid + i * 256;
            int r = q >> 3, kq = q & 7;
            uint32_t off = (uint32_t)(r * 80 + (kq >> 1) * 16 + (kq & 1) * 8);
            uint32_t h0, l0, h1, l1;
            bsplit2(va[i].x, va[i].y, h0, l0);
            bsplit2(va[i].z, va[i].w, h1, l1);
            *reinterpret_cast<uint2*>(sm + s * FSBUF + off)              = make_uint2(h0, h1);
            *reinterpret_cast<uint2*>(sm + s * FSBUF + FPLANE + off)     = make_uint2(l0, l1);
            bsplit2(vb[i].x, vb[i].y, h0, l0);
            bsplit2(vb[i].z, vb[i].w, h1, l1);
            *reinterpret_cast<uint2*>(sm + s * FSBUF + 2 * FPLANE + off) = make_uint2(h0, h1);
            *reinterpret_cast<uint2*>(sm + s * FSBUF + 3 * FPLANE + off) = make_uint2(l0, l1);
        }
    };

    LDG(0); STS(0);
    __syncthreads();

    int cur = 0;
    for (int kt = 0; kt < 32; kt++) {
        if (kt + 1 < 32) LDG(kt + 1);
        const uint32_t base = sb + cur * FSBUF;
#pragma unroll
        for (int ks = 0; ks < 2; ks++) {
            uint32_t ah[4][4], al[4][4], bh[2][4], bl[2][4];
#pragma unroll
            for (int mi = 0; mi < 4; mi++) {
                uint32_t ad = base + (uint32_t)((aRow + mi * 16) * 80 + (aChk + ks * 2) * 16);
                ldsm4(ah[mi], ad);
                ldsm4(al[mi], ad + FPLANE);
            }
#pragma unroll
            for (int pr = 0; pr < 2; pr++) {
                uint32_t bd = base + 2 * FPLANE +
                              (uint32_t)((wn + pr * 16 + bRowOff) * 80 + (bChk + ks * 2) * 16);
                ldsm4(bh[pr], bd);
                ldsm4(bl[pr], bd + FPLANE);
            }
#pragma unroll
            for (int mi = 0; mi < 4; mi++)
#pragma unroll
                for (int ni = 0; ni < 4; ni++) {
                    const int pr = ni >> 1, o = (ni & 1) * 2;
                    mma16816(acc[mi][ni], ah[mi], bh[pr][o], bh[pr][o + 1]);
                    mma16816(acc[mi][ni], ah[mi], bl[pr][o], bl[pr][o + 1]);
                    mma16816(acc[mi][ni], al[mi], bh[pr][o], bh[pr][o + 1]);
                }
        }
        if (kt + 1 < 32) {
            int nxt = cur ^ 1;
            STS(nxt);
            __syncthreads();
            cur = nxt;
        }
    }

    const int l4 = lane >> 2, l2 = (lane & 3) * 2;
#pragma unroll
    for (int mi = 0; mi < 4; mi++) {
        int r0 = rowBase + wr + mi * 16 + l4;
#pragma unroll
        for (int ni = 0; ni < 4; ni++) {
            int c = colBase + wn + ni * 8 + l2;
            float2 bb = *reinterpret_cast<const float2*>(bias + c);
            *reinterpret_cast<float2*>(C + (size_t)r0 * H_SZ + c) =
                make_float2(tanhf(acc[mi][ni][0] + bb.x), tanhf(acc[mi][ni][1] + bb.y));
            *reinterpret_cast<float2*>(C + (size_t)(r0 + 8) * H_SZ + c) =
                make_float2(tanhf(acc[mi][ni][2] + bb.x), tanhf(acc[mi][ni][3] + bb.y));
        }
    }
}

// =====================================================================
// prep kernels
// =====================================================================

// one block per W row: Wh bf16 + qW (full value) + qWl (bf16-lo * 256) + scale
__global__ void __launch_bounds__(256)
conv_wq(const float* __restrict__ W, __nv_bfloat16* __restrict__ Wh,
        uint8_t* __restrict__ qW, uint8_t* __restrict__ qWl, float* __restrict__ sW)
{
    __shared__ float wred[8];
    const int j = blockIdx.x, tid = threadIdx.x, lane = tid & 31, wid = tid >> 5;
    float4 v = *reinterpret_cast<const float4*>(W + (size_t)j * H_SZ + tid * 4);
    float m = fmaxf(fmaxf(fabsf(v.x), fabsf(v.y)), fmaxf(fabsf(v.z), fabsf(v.w)));
#pragma unroll
    for (int o = 16; o > 0; o >>= 1) m = fmaxf(m, __shfl_xor_sync(0xffffffffu, m, o));
    if (lane == 0) wred[wid] = m;
    __syncthreads();
    float mall = wred[0];
#pragma unroll
    for (int i = 1; i < 8; i++) mall = fmaxf(mall, wred[i]);
    float inv = mall > 0.0f ? 127.0f / mall : 0.0f;
    if (tid == 0) sW[j] = mall * (1.0f / 127.0f);

    uint32_t h0, l0, h1, l1;
    bsplit2(v.x, v.y, h0, l0);
    bsplit2(v.z, v.w, h1, l1);
    *reinterpret_cast<uint2*>(Wh + (size_t)j * H_SZ + tid * 4) = make_uint2(h0, h1);
    __nv_bfloat16 bx = __float2bfloat16_rn(v.x), by = __float2bfloat16_rn(v.y);
    __nv_bfloat16 bz = __float2bfloat16_rn(v.z), bw = __float2bfloat16_rn(v.w);
    float lx = v.x - __bfloat162float(bx), ly = v.y - __bfloat162float(by);
    float lz = v.z - __bfloat162float(bz), lw = v.w - __bfloat162float(bw);
    *reinterpret_cast<uint32_t*>(qW  + (size_t)j * H_SZ + tid * 4) = q8x4(v.x, v.y, v.z, v.w, inv);
    *reinterpret_cast<uint32_t*>(qWl + (size_t)j * H_SZ + tid * 4) = q8x4(lx, ly, lz, lw, inv * 256.0f);
}

__global__ void conv_w0t(const float* __restrict__ W0, float* __restrict__ W0T)
{
    int idx = blockIdx.x * blockDim.x + threadIdx.x;
    int d = idx >> 10, k = idx & (H_SZ - 1);
    W0T[idx] = W0[k * 33 + d];
}

// U1 rows: bf16 hi + int8 (value, lo*256) + per-row scale. One block per sample.
__global__ void __launch_bounds__(256)
prep_u1(const float* __restrict__ h1, const float* __restrict__ W0T,
        __nv_bfloat16* __restrict__ U1h, uint8_t* __restrict__ qU1,
        uint8_t* __restrict__ qU1l, float* __restrict__ sU1)
{
    __shared__ float s1[H_SZ];
    __shared__ float wred[8];
    __shared__ float sinv;
    const int b = blockIdx.x, tid = threadIdx.x, lane = tid & 31, wid = tid >> 5;
    {
        float4 h = *reinterpret_cast<const float4*>(h1 + (size_t)b * H_SZ + tid * 4);
        s1[tid * 4 + 0] = 1.0f - h.x * h.x;
        s1[tid * 4 + 1] = 1.0f - h.y * h.y;
        s1[tid * 4 + 2] = 1.0f - h.z * h.z;
        s1[tid * 4 + 3] = 1.0f - h.w * h.w;
    }
    __syncthreads();
#pragma unroll 1
    for (int d = 0; d < 32; d++) {
        float4 w = *reinterpret_cast<const float4*>(W0T + d * H_SZ + tid * 4);
        float u0 = s1[tid * 4 + 0] * w.x, u1 = s1[tid * 4 + 1] * w.y;
        float u2 = s1[tid * 4 + 2] * w.z, u3 = s1[tid * 4 + 3] * w.w;
        float m = fmaxf(fmaxf(fabsf(u0), fabsf(u1)), fmaxf(fabsf(u2), fabsf(u3)));
#pragma unroll
        for (int o = 16; o > 0; o >>= 1) m = fmaxf(m, __shfl_xor_sync(0xffffffffu, m, o));
        if (lane == 0) wred[wid] = m;
        __syncthreads();
        if (tid == 0) {
            float mall = wred[0];
#pragma unroll
            for (int i = 1; i < 8; i++) mall = fmaxf(mall, wred[i]);
            sinv = mall > 0.0f ? 127.0f / mall : 0.0f;
            sU1[b * 32 + d] = mall * (1.0f / 127.0f);
        }
        __syncthreads();
        float inv = sinv;
        uint32_t h0, l0u, h1b, l1u;
        bsplit2(u0, u1, h0, l0u);
        bsplit2(u2, u3, h1b, l1u);
        __nv_bfloat16 b0 = __float2bfloat16_rn(u0), b1 = __float2bfloat16_rn(u1);
        __nv_bfloat16 b2 = __float2bfloat16_rn(u2), b3 = __float2bfloat16_rn(u3);
        float l0 = u0 - __bfloat162float(b0), l1 = u1 - __bfloat162float(b1);
        float l2 = u2 - __bfloat162float(b2), l3 = u3 - __bfloat162float(b3);
        size_t base = ((size_t)(b * 32 + d) << 10) + tid * 4;
        *reinterpret_cast<uint2*>(U1h + base) = make_uint2(h0, h1b);
        *reinterpret_cast<uint32_t*>(qU1 + base)  = q8x4(u0, u1, u2, u3, inv);
        *reinterpret_cast<uint32_t*>(qU1l + base) = q8x4(l0, l1, l2, l3, inv * 256.0f);
        __syncthreads();
    }
}

// per-row quant of U2 from bf16 hi/lo planes. One block per row.
__global__ void __launch_bounds__(256)
quant_u2(const __nv_bfloat16* __restrict__ U2h, const __nv_bfloat16* __restrict__ U2l,
         uint8_t* __restrict__ qU2, uint8_t* __restrict__ qU2l, float* __restrict__ sU2)
{
    __shared__ float wred[8];
    __shared__ float sinv;
    const int r = blockIdx.x, tid = threadIdx.x, lane = tid & 31, wid = tid >> 5;
    size_t base = ((size_t)r << 10) + tid * 4;
    uint2 hu = *reinterpret_cast<const uint2*>(U2h + base);
    uint2 lu = *reinterpret_cast<const uint2*>(U2l + base);
    __nv_bfloat162 h01 = *reinterpret_cast<__nv_bfloat162*>(&hu.x);
    __nv_bfloat162 h23 = *reinterpret_cast<__nv_bfloat162*>(&hu.y);
    __nv_bfloat162 l01 = *reinterpret_cast<__nv_bfloat162*>(&lu.x);
    __nv_bfloat162 l23 = *reinterpret_cast<__nv_bfloat162*>(&lu.y);
    float l0 = __bfloat162float(l01.x), l1 = __bfloat162float(l01.y);
    float l2 = __bfloat162float(l23.x), l3 = __bfloat162float(l23.y);
    float v0 = __bfloat162float(h01.x) + l0, v1 = __bfloat162float(h01.y) + l1;
    float v2 = __bfloat162float(h23.x) + l2, v3 = __bfloat162float(h23.y) + l3;
    float m = fmaxf(fmaxf(fabsf(v0), fabsf(v1)), fmaxf(fabsf(v2), fabsf(v3)));
#pragma unroll
    for (int o = 16; o > 0; o >>= 1) m = fmaxf(m, __shfl_xor_sync(0xffffffffu, m, o));
    if (lane == 0) wred[wid] = m;
    __syncthreads();
    if (tid == 0) {
        float mall = wred[0];
#pragma unroll
        for (int i = 1; i < 8; i++) mall = fmaxf(mall, wred[i]);
        sinv = mall > 0.0f ? 127.0f / mall : 0.0f;
        sU2[r] = mall * (1.0f / 127.0f);
    }
    __syncthreads();
    float inv = sinv;
    *reinterpret_cast<uint32_t*>(qU2 + base)  = q8x4(v0, v1, v2, v3, inv);
    *reinterpret_cast<uint32_t*>(qU2l + base) = q8x4(l0, l1, l2, l3, inv * 256.0f);
}

__global__ void layer0_kernel(const float* __restrict__ t, const float* __restrict__ z,
                              const float* __restrict__ W0, const float* __restrict__ b0,
                              float* __restrict__ h1)
{
    int idx = blockIdx.x * blockDim.x + threadIdx.x;
    int j = idx & (H_SZ - 1);
    int b = idx >> 10;
    const float* w  = W0 + j * 33;
    const float* zr = z + b * D_SZ;
    float acc = b0[j] + t[0] * w[32];
#pragma unroll
    for (int d = 0; d < 32; d++) acc = fmaf(zr[d], w[d], acc);
    h1[idx] = tanhf(acc);
}

__global__ void __launch_bounds__(256, 4)
out_kernel2(const float* __restrict__ h3, const float* __restrict__ W3,
            const float* __restrict__ b3, float* __restrict__ out)
{
    const int b = blockIdx.x;
    const int wid = threadIdx.x >> 5, lid = threadIdx.x & 31;
    const float* h = h3 + (size_t)b * H_SZ;
#pragma unroll
    for (int dd = 0; dd < 4; dd++) {
        const int d = wid * 4 + dd;
        const float* w = W3 + (size_t)d * H_SZ;
        float acc = 0.0f;
#pragma unroll 4
        for (int k = lid; k < H_SZ; k += 32) acc = fmaf(h[k], w[k], acc);
#pragma unroll
        for (int o = 16; o > 0; o >>= 1) acc += __shfl_xor_sync(0xffffffffu, acc, o);
        if (lid == 0) out[b * D_SZ + d] = acc + b3[d];
    }
}

__global__ void fin_kernel(float* __restrict__ out)
{
    int b = blockIdx.x * blockDim.x + threadIdx.x;
    if (b < B_SZ) {
        float s = 0.0f;
#pragma unroll
        for (int x = 0; x < 8; x++) s += g_tpart[x * B_SZ + b];
        out[B_SZ * D_SZ + b] = -s;
    }
}

// ---------------- launch ----------------
extern "C" void kernel_launch(void* const* d_in, const int* in_sizes, int n_in,
                              void* d_out, int out_size)
{
    const float* t  = (const float*)d_in[0];
    const float* z  = (const float*)d_in[1];
    const float* W0 = (const float*)d_in[2];
    const float* b0 = (const float*)d_in[3];
    const float* W1 = (const float*)d_in[4];
    const float* b1 = (const float*)d_in[5];
    const float* W2 = (const float*)d_in[6];
    const float* b2 = (const float*)d_in[7];
    const float* W3 = (const float*)d_in[8];
    const float* b3 = (const float*)d_in[9];
    float* out = (float*)d_out;

    float *ph1, *ph2, *ph3, *pW0T, *psU1, *psU2, *psW1, *psW2;
    __nv_bfloat16 *pU1h, *pU2h, *pU2l, *pW1h, *pW2h;
    uint8_t *pqU1, *pqU1l, *pqU2, *pqU2l, *pqW1, *pqW1l, *pqW2, *pqW2l;
    cudaGetSymbolAddress((void**)&ph1, g_h1);
    cudaGetSymbolAddress((void**)&ph2, g_h2);
    cudaGetSymbolAddress((void**)&ph3, g_h3);
    cudaGetSymbolAddress((void**)&pW0T, g_W0T);
    cudaGetSymbolAddress((void**)&pU1h, g_U1h);
    cudaGetSymbolAddress((void**)&pU2h, g_U2h);
    cudaGetSymbolAddress((void**)&pU2l, g_U2l);
    cudaGetSymbolAddress((void**)&pqU1, g_qU1);
    cudaGetSymbolAddress((void**)&pqU1l, g_qU1l);
    cudaGetSymbolAddress((void**)&pqU2, g_qU2);
    cudaGetSymbolAddress((void**)&pqU2l, g_qU2l);
    cudaGetSymbolAddress((void**)&pW1h, g_W1h);
    cudaGetSymbolAddress((void**)&pW2h, g_W2h);
    cudaGetSymbolAddress((void**)&pqW1, g_qW1);
    cudaGetSymbolAddress((void**)&pqW1l, g_qW1l);
    cudaGetSymbolAddress((void**)&pqW2, g_qW2);
    cudaGetSymbolAddress((void**)&pqW2l, g_qW2l);
    cudaGetSymbolAddress((void**)&psU1, g_sU1);
    cudaGetSymbolAddress((void**)&psU2, g_sU2);
    cudaGetSymbolAddress((void**)&psW1, g_sW1);
    cudaGetSymbolAddress((void**)&psW2, g_sW2);

    cudaFuncSetAttribute(fwd_gemm, cudaFuncAttributeMaxDynamicSharedMemorySize, SMEM_FWD);
    cudaFuncSetAttribute(tan2<1>,  cudaFuncAttributeMaxDynamicSharedMemorySize, SMEM_TAN);
    cudaFuncSetAttribute(tan2<2>,  cudaFuncAttributeMaxDynamicSharedMemorySize, SMEM_TAN);

    // prep
    layer0_kernel<<<(B_SZ * H_SZ) / 256, 256>>>(t, z, W0, b0, ph1);
    conv_w0t<<<(D_SZ * H_SZ) / 256, 256>>>(W0, pW0T);
    conv_wq<<<H_SZ, 256>>>(W1, pW1h, pqW1, pqW1l, psW1);
    conv_wq<<<H_SZ, 256>>>(W2, pW2h, pqW2, pqW2l, psW2);
    prep_u1<<<B_SZ, 256>>>(ph1, pW0T, pU1h, pqU1, pqU1l, psU1);

    // forward
    dim3 gF(H_SZ / 128, B_SZ / 128);
    fwd_gemm<<<gF, 256, SMEM_FWD>>>(ph1, W1, b1, ph2);
    fwd_gemm<<<gF, 256, SMEM_FWD>>>(ph2, W2, b2, ph3);
    out_kernel2<<<B_SZ, 256>>>(ph3, W3, b3, out);

    // tangent chain: GEMM1 -> quantize U2 -> GEMM2
    dim3 gT(H_SZ / 128, MT / 128);
    tan2<1><<<gT, 256, SMEM_TAN>>>(pU1h, pqU1, pqU1l, psU1, pW1h, pqW1, pqW1l, psW1,
                                   ph2, nullptr, pU2h, pU2l);
    quant_u2<<<MT, 256>>>(pU2h, pU2l, pqU2, pqU2l, psU2);
    tan2<2><<<gT, 256, SMEM_TAN>>>(pU2h, pqU2, pqU2l, psU2, pW2h, pqW2, pqW2l, psW2,
                                   ph3, W3, nullptr, nullptr);

    fin_kernel<<<(B_SZ + 255) / 256, 256>>>(out);
}

// round 17
// speedup vs baseline: 1.0564x; 1.0564x over previous
#include <cuda_runtime.h>
#include <cuda_bf16.h>
#include <math.h>
#include <stdint.h>

#define B_SZ 4096
#define D_SZ 32
#define H_SZ 1024
#define MT   (B_SZ * D_SZ)

// ---------------- scratch ----------------
__device__ float g_h1[B_SZ * H_SZ];
__device__ float g_h2[B_SZ * H_SZ];
__device__ float g_h3[B_SZ * H_SZ];
__device__ float g_W0T[D_SZ * H_SZ];
__device__ __nv_bfloat16 g_U1h[(size_t)MT * H_SZ];
__device__ __nv_bfloat16 g_U2h[(size_t)MT * H_SZ];
__device__ __nv_bfloat16 g_U2l[(size_t)MT * H_SZ];
__device__ __align__(256) uint8_t g_qU1 [(size_t)MT * H_SZ];
__device__ __align__(256) uint8_t g_qU1l[(size_t)MT * H_SZ];
__device__ __align__(256) uint8_t g_qU2 [(size_t)MT * H_SZ];
__device__ __align__(256) uint8_t g_qU2l[(size_t)MT * H_SZ];
__device__ __nv_bfloat16 g_W1h[H_SZ * H_SZ], g_W2h[H_SZ * H_SZ];
__device__ __align__(256) uint8_t g_qW1[H_SZ * H_SZ], g_qW1l[H_SZ * H_SZ];
__device__ __align__(256) uint8_t g_qW2[H_SZ * H_SZ], g_qW2l[H_SZ * H_SZ];
__device__ float g_sU1[MT], g_sU2[MT], g_sW1[H_SZ], g_sW2[H_SZ];
__device__ float g_tpart[8 * B_SZ];

// ---------------- helpers ----------------
__device__ __forceinline__ uint32_t smem_u32_of(const void* p) {
    uint32_t a;
    asm("{ .reg .u64 t; cvta.to.shared.u64 t, %1; cvt.u32.u64 %0, t; }" : "=r"(a) : "l"(p));
    return a;
}
__device__ __forceinline__ void ldsm4(uint32_t r[4], uint32_t addr) {
    asm volatile("ldmatrix.sync.aligned.m8n8.x4.shared.b16 {%0,%1,%2,%3}, [%4];"
                 : "=r"(r[0]), "=r"(r[1]), "=r"(r[2]), "=r"(r[3]) : "r"(addr));
}
__device__ __forceinline__ void mma16816(float c[4], const uint32_t a[4],
                                         uint32_t b0, uint32_t b1) {
    asm volatile("mma.sync.aligned.m16n8k16.row.col.f32.bf16.bf16.f32 "
                 "{%0,%1,%2,%3}, {%4,%5,%6,%7}, {%8,%9}, {%0,%1,%2,%3};"
                 : "+f"(c[0]), "+f"(c[1]), "+f"(c[2]), "+f"(c[3])
                 : "r"(a[0]), "r"(a[1]), "r"(a[2]), "r"(a[3]), "r"(b0), "r"(b1));
}
__device__ __forceinline__ void imma16832(int c[4], const uint32_t a[4],
                                          uint32_t b0, uint32_t b1) {
    asm volatile("mma.sync.aligned.m16n8k32.row.col.s32.s8.s8.s32 "
                 "{%0,%1,%2,%3}, {%4,%5,%6,%7}, {%8,%9}, {%0,%1,%2,%3};"
                 : "+r"(c[0]), "+r"(c[1]), "+r"(c[2]), "+r"(c[3])
                 : "r"(a[0]), "r"(a[1]), "r"(a[2]), "r"(a[3]), "r"(b0), "r"(b1));
}
__device__ __forceinline__ void bsplit2(float x, float y, uint32_t& hi, uint32_t& lo) {
    __nv_bfloat16 hx = __float2bfloat16_rn(x), hy = __float2bfloat16_rn(y);
    __nv_bfloat16 lx = __float2bfloat16_rn(x - __bfloat162float(hx));
    __nv_bfloat16 ly = __float2bfloat16_rn(y - __bfloat162float(hy));
    hi = (uint32_t)__bfloat16_as_ushort(hx) | ((uint32_t)__bfloat16_as_ushort(hy) << 16);
    lo = (uint32_t)__bfloat16_as_ushort(lx) | ((uint32_t)__bfloat16_as_ushort(ly) << 16);
}
__device__ __forceinline__ uint32_t q8x4(float a, float b, float c, float d, float inv) {
    int q0 = max(-127, min(127, __float2int_rn(a * inv)));
    int q1 = max(-127, min(127, __float2int_rn(b * inv)));
    int q2 = max(-127, min(127, __float2int_rn(c * inv)));
    int q3 = max(-127, min(127, __float2int_rn(d * inv)));
    return (uint32_t)(q0 & 255) | ((uint32_t)(q1 & 255) << 8) |
           ((uint32_t)(q2 & 255) << 16) | ((uint32_t)(q3 & 255) << 24);
}
__device__ __forceinline__ void cpa16(uint32_t dst, const void* src) {
    asm volatile("cp.async.cg.shared.global [%0], [%1], 16;" :: "r"(dst), "l"(src));
}
#define CP_COMMIT() asm volatile("cp.async.commit_group;" ::: "memory")
#define CP_WAIT0()  asm volatile("cp.async.wait_group 0;" ::: "memory")
#define CP_WAIT1()  asm volatile("cp.async.wait_group 1;" ::: "memory")

// =====================================================================
// Tangent GEMM v3: PHASE-SPLIT. Phase 1 = int8 cross terms over full K
// into I[4][4][4]; fold into fp32; Phase 2 = bf16 hi*hi over full K into
// acc. Never holds both accumulator sets + fragments live -> no spills.
// Block 128x128, 8 warps (64x32), k-tile 32, 3-stage cp.async per phase.
// Phase1 stage: 4 int8 planes @48B pitch = 24576 B
// Phase2 stage: 2 bf16 planes @80B pitch = 20480 B
// =====================================================================
#define P1_QA  0
#define P1_QAL 6144
#define P1_QBL 12288
#define P1_QBH 18432
#define P1_STG 24576
#define P2_AH  0
#define P2_BH  10240
#define P2_STG 20480
#define SMEM_TAN (3 * P1_STG)   /* 73728 B */

template <int MODE>
__global__ void __launch_bounds__(256, 1)
tan3(const __nv_bfloat16* __restrict__ Ahb, const uint8_t* __restrict__ qAg,
     const uint8_t* __restrict__ qAlg, const float* __restrict__ sAg,
     const __nv_bfloat16* __restrict__ Bhb, const uint8_t* __restrict__ qBg,
     const uint8_t* __restrict__ qBlg, const float* __restrict__ sBg,
     const float* __restrict__ hs, const float* __restrict__ W3p,
     __nv_bfloat16* __restrict__ U2h, __nv_bfloat16* __restrict__ U2l)
{
    extern __shared__ char sm[];
    __shared__ float red[4][4];
    const uint32_t sb = smem_u32_of(sm);
    const int tid = threadIdx.x, lane = tid & 31, wid = tid >> 5;
    const int warpM = wid >> 2, warpN = wid & 3;
    const int wr = warpM * 64, wn = warpN * 32;
    const int rowBase = blockIdx.y * 128, colBase = blockIdx.x * 128;

    // lane-derived ldmatrix addressing
    const int aRow = wr + (lane & 15);
    const int aChk = lane >> 4;
    const int bRowOff = ((lane >> 4) << 3) + (lane & 7);
    const int bChk = (lane >> 3) & 1;

    // cp.async thread assignments
    const int r8 = tid >> 1, k8 = tid & 1;                 // int8 planes: 1 chunk each
    const int rA0 = (tid * 2) >> 2,     kA0 = (tid * 2) & 3;
    const int rA1 = (tid * 2 + 1) >> 2, kA1 = (tid * 2 + 1) & 3;

    float acc[4][4][4];

    // ================= PHASE 1: int8 cross terms =================
    {
        int I[4][4][4];
#pragma unroll
        for (int a = 0; a < 4; a++)
#pragma unroll
            for (int b = 0; b < 4; b++)
#pragma unroll
                for (int c = 0; c < 4; c++) I[a][b][c] = 0;

        auto ISSUE8 = [&](int kt) {
            const uint32_t s0 = sb + (uint32_t)(kt % 3) * P1_STG;
            const int kb = kt * 32;
            const uint32_t off8 = (uint32_t)(r8 * 48 + k8 * 16);
            const size_t gA = (((size_t)(rowBase + r8)) << 10) + kb + k8 * 16;
            const size_t gB = (((size_t)(colBase + r8)) << 10) + kb + k8 * 16;
            cpa16(s0 + P1_QA  + off8, qAg  + gA);
            cpa16(s0 + P1_QAL + off8, qAlg + gA);
            cpa16(s0 + P1_QBL + off8, qBlg + gB);
            cpa16(s0 + P1_QBH + off8, qBg  + gB);
            CP_COMMIT();
        };

        ISSUE8(0);
        ISSUE8(1);

        for (int kt = 0; kt < 32; kt++) {
            if (kt < 31) { CP_WAIT1(); } else { CP_WAIT0(); }
            __syncthreads();
            if (kt + 2 < 32) ISSUE8(kt + 2);

            const uint32_t base = sb + (uint32_t)(kt % 3) * P1_STG;
            uint32_t qa[4][4], qal[4][4], qb[2][4], qbl[2][4];
#pragma unroll
            for (int mi = 0; mi < 4; mi++) {
                uint32_t ad = base + P1_QA + (uint32_t)((aRow + mi * 16) * 48 + aChk * 16);
                ldsm4(qa[mi], ad);
                ldsm4(qal[mi], ad + (P1_QAL - P1_QA));
            }
#pragma unroll
            for (int pr = 0; pr < 2; pr++) {
                uint32_t bd = base + P1_QBL + (uint32_t)((wn + pr * 16 + bRowOff) * 48 + bChk * 16);
                ldsm4(qbl[pr], bd);
                ldsm4(qb[pr],  bd + (P1_QBH - P1_QBL));
            }
#pragma unroll
            for (int mi = 0; mi < 4; mi++)
#pragma unroll
                for (int ni = 0; ni < 4; ni++) {
                    const int pr = ni >> 1, o = (ni & 1) * 2;
                    imma16832(I[mi][ni], qa[mi],  qbl[pr][o], qbl[pr][o + 1]);
                    imma16832(I[mi][ni], qal[mi], qb[pr][o],  qb[pr][o + 1]);
                }
        }

        // all phase-1 smem reads done before phase-2 prologue overwrites
        __syncthreads();

        // phase-2 prologue issued BEFORE the fold so loads fly during it
        {
            auto ISSUE16 = [&](int kt) {
                const uint32_t s0 = sb + (uint32_t)(kt % 3) * P2_STG;
                const int kb = kt * 32;
                cpa16(s0 + P2_AH + rA0 * 80 + kA0 * 16,
                      Ahb + (((size_t)(rowBase + rA0)) << 10) + kb + kA0 * 8);
                cpa16(s0 + P2_AH + rA1 * 80 + kA1 * 16,
                      Ahb + (((size_t)(rowBase + rA1)) << 10) + kb + kA1 * 8);
                cpa16(s0 + P2_BH + rA0 * 80 + kA0 * 16,
                      Bhb + (((size_t)(colBase + rA0)) << 10) + kb + kA0 * 8);
                cpa16(s0 + P2_BH + rA1 * 80 + kA1 * 16,
                      Bhb + (((size_t)(colBase + rA1)) << 10) + kb + kA1 * 8);
                CP_COMMIT();
            };
            ISSUE16(0);
            ISSUE16(1);
        }

        // fold: acc = I * (sA*sB/256)
        const int l4 = lane >> 2, l2 = (lane & 3) * 2;
        float sa0[4], sa1[4], sb0[4], sb1[4];
#pragma unroll
        for (int mi = 0; mi < 4; mi++) {
            int r = rowBase + wr + mi * 16 + l4;
            sa0[mi] = sAg[r]; sa1[mi] = sAg[r + 8];
        }
#pragma unroll
        for (int ni = 0; ni < 4; ni++) {
            int c = colBase + wn + ni * 8 + l2;
            sb0[ni] = sBg[c]; sb1[ni] = sBg[c + 1];
        }
        const float K8 = 1.0f / 256.0f;
#pragma unroll
        for (int mi = 0; mi < 4; mi++)
#pragma unroll
            for (int ni = 0; ni < 4; ni++) {
                acc[mi][ni][0] = (float)I[mi][ni][0] * (K8 * sa0[mi] * sb0[ni]);
                acc[mi][ni][1] = (float)I[mi][ni][1] * (K8 * sa0[mi] * sb1[ni]);
                acc[mi][ni][2] = (float)I[mi][ni][2] * (K8 * sa1[mi] * sb0[ni]);
                acc[mi][ni][3] = (float)I[mi][ni][3] * (K8 * sa1[mi] * sb1[ni]);
            }
    }

    // ================= PHASE 2: bf16 hi*hi =================
    {
        auto ISSUE16 = [&](int kt) {
            const uint32_t s0 = sb + (uint32_t)(kt % 3) * P2_STG;
            const int kb = kt * 32;
            cpa16(s0 + P2_AH + rA0 * 80 + kA0 * 16,
                  Ahb + (((size_t)(rowBase + rA0)) << 10) + kb + kA0 * 8);
            cpa16(s0 + P2_AH + rA1 * 80 + kA1 * 16,
                  Ahb + (((size_t)(rowBase + rA1)) << 10) + kb + kA1 * 8);
            cpa16(s0 + P2_BH + rA0 * 80 + kA0 * 16,
                  Bhb + (((size_t)(colBase + rA0)) << 10) + kb + kA0 * 8);
            cpa16(s0 + P2_BH + rA1 * 80 + kA1 * 16,
                  Bhb + (((size_t)(colBase + rA1)) << 10) + kb + kA1 * 8);
            CP_COMMIT();
        };

        for (int kt = 0; kt < 32; kt++) {
            if (kt < 31) { CP_WAIT1(); } else { CP_WAIT0(); }
            __syncthreads();
            if (kt + 2 < 32) ISSUE16(kt + 2);

            const uint32_t base = sb + (uint32_t)(kt % 3) * P2_STG;
#pragma unroll
            for (int ks = 0; ks < 2; ks++) {
                uint32_t ah[4][4], bh[2][4];
#pragma unroll
                for (int mi = 0; mi < 4; mi++)
                    ldsm4(ah[mi], base + P2_AH + (uint32_t)((aRow + mi * 16) * 80 + (aChk + ks * 2) * 16));
#pragma unroll
                for (int pr = 0; pr < 2; pr++)
                    ldsm4(bh[pr], base + P2_BH + (uint32_t)((wn + pr * 16 + bRowOff) * 80 + (bChk + ks * 2) * 16));
#pragma unroll
                for (int mi = 0; mi < 4; mi++)
#pragma unroll
                    for (int ni = 0; ni < 4; ni++) {
                        const int pr = ni >> 1, o = (ni & 1) * 2;
                        mma16816(acc[mi][ni], ah[mi], bh[pr][o], bh[pr][o + 1]);
                    }
            }
        }
    }

    // ---- epilogues ----
    const int l4 = lane >> 2, l2 = (lane & 3) * 2;

    if (MODE == 1) {
#pragma unroll
        for (int mi = 0; mi < 4; mi++) {
            int r0 = rowBase + wr + mi * 16 + l4;
            int b = r0 >> 5;
#pragma unroll
            for (int ni = 0; ni < 4; ni++) {
                int c = colBase + wn + ni * 8 + l2;
                float2 h = *reinterpret_cast<const float2*>(hs + (size_t)b * H_SZ + c);
                float s0 = 1.0f - h.x * h.x, s1 = 1.0f - h.y * h.y;
                uint32_t hi, lo;
                bsplit2(acc[mi][ni][0] * s0, acc[mi][ni][1] * s1, hi, lo);
                *reinterpret_cast<uint32_t*>(U2h + (size_t)r0 * H_SZ + c) = hi;
                *reinterpret_cast<uint32_t*>(U2l + (size_t)r0 * H_SZ + c) = lo;
                bsplit2(acc[mi][ni][2] * s0, acc[mi][ni][3] * s1, hi, lo);
                *reinterpret_cast<uint32_t*>(U2h + (size_t)(r0 + 8) * H_SZ + c) = hi;
                *reinterpret_cast<uint32_t*>(U2l + (size_t)(r0 + 8) * H_SZ + c) = lo;
            }
        }
    } else {
        float p[2] = {0.0f, 0.0f};
#pragma unroll
        for (int mi = 0; mi < 4; mi++) {
            int r0 = rowBase + wr + mi * 16 + l4;
            int b = r0 >> 5, d0 = r0 & 31;
#pragma unroll
            for (int ni = 0; ni < 4; ni++) {
                int c = colBase + wn + ni * 8 + l2;
                float2 h  = *reinterpret_cast<const float2*>(hs + (size_t)b * H_SZ + c);
                float s0 = 1.0f - h.x * h.x, s1 = 1.0f - h.y * h.y;
                float2 w0 = *reinterpret_cast<const float2*>(W3p + (size_t)d0 * H_SZ + c);
                float2 w1 = *reinterpret_cast<const float2*>(W3p + (size_t)(d0 + 8) * H_SZ + c);
                p[mi >> 1] += acc[mi][ni][0] * s0 * w0.x + acc[mi][ni][1] * s1 * w0.y
                            + acc[mi][ni][2] * s0 * w1.x + acc[mi][ni][3] * s1 * w1.y;
            }
        }
#pragma unroll
        for (int j = 0; j < 2; j++) {
            float v = p[j];
#pragma unroll
            for (int o = 16; o > 0; o >>= 1) v += __shfl_xor_sync(0xffffffffu, v, o);
            if (lane == 0) red[warpM * 2 + j][warpN] = v;
        }
        __syncthreads();
        if (tid < 4) {
            float s = red[tid][0] + red[tid][1] + red[tid][2] + red[tid][3];
            g_tpart[blockIdx.x * B_SZ + (rowBase >> 5) + tid] = s;
        }
    }
}

// =====================================================================
// Forward GEMM (unchanged, passing)
// =====================================================================
#define FPLANE 10240
#define FSBUF  (4 * FPLANE)
#define SMEM_FWD (2 * FSBUF)

__global__ void __launch_bounds__(256, 1)
fwd_gemm(const float* __restrict__ A, const float* __restrict__ W,
         const float* __restrict__ bias, float* __restrict__ C)
{
    extern __shared__ char sm[];
    const uint32_t sb = smem_u32_of(sm);
    const int tid = threadIdx.x, lane = tid & 31, wid = tid >> 5;
    const int warpM = wid >> 2, warpN = wid & 3;
    const int wr = warpM * 64, wn = warpN * 32;
    const int rowBase = blockIdx.y * 128, colBase = blockIdx.x * 128;

    float acc[4][4][4];
#pragma unroll
    for (int a = 0; a < 4; a++)
#pragma unroll
        for (int b = 0; b < 4; b++)
#pragma unroll
            for (int c = 0; c < 4; c++) acc[a][b][c] = 0.0f;

    const int aRow = wr + (lane & 15);
    const int aChk = lane >> 4;
    const int bRowOff = ((lane >> 4) << 3) + (lane & 7);
    const int bChk = (lane >> 3) & 1;

    float4 va[4], vb[4];
    auto LDG = [&](int kt) {
        const int kb = kt * 32;
#pragma unroll
        for (int i = 0; i < 4; i++) {
            int q = tid + i * 256;
            int r = q >> 3, kq = q & 7, k0 = kb + kq * 4;
            va[i] = *reinterpret_cast<const float4*>(A + (size_t)(rowBase + r) * H_SZ + k0);
            vb[i] = *reinterpret_cast<const float4*>(W + (size_t)(colBase + r) * H_SZ + k0);
        }
    };
    auto STS = [&](int s) {
#pragma unroll
        for (int i = 0; i < 4; i++) {
            int q = tid + i * 256;
            int r = q >> 3, kq = q & 7;
            uint32_t off = (uint32_t)(r * 80 + (kq >> 1) * 16 + (kq & 1) * 8);
            uint32_t h0, l0, h1, l1;
            bsplit2(va[i].x, va[i].y, h0, l0);
            bsplit2(va[i].z, va[i].w, h1, l1);
            *reinterpret_cast<uint2*>(sm + s * FSBUF + off)              = make_uint2(h0, h1);
            *reinterpret_cast<uint2*>(sm + s * FSBUF + FPLANE + off)     = make_uint2(l0, l1);
            bsplit2(vb[i].x, vb[i].y, h0, l0);
            bsplit2(vb[i].z, vb[i].w, h1, l1);
            *reinterpret_cast<uint2*>(sm + s * FSBUF + 2 * FPLANE + off) = make_uint2(h0, h1);
            *reinterpret_cast<uint2*>(sm + s * FSBUF + 3 * FPLANE + off) = make_uint2(l0, l1);
        }
    };

    LDG(0); STS(0);
    __syncthreads();

    int cur = 0;
    for (int kt = 0; kt < 32; kt++) {
        if (kt + 1 < 32) LDG(kt + 1);
        const uint32_t base = sb + cur * FSBUF;
#pragma unroll
        for (int ks = 0; ks < 2; ks++) {
            uint32_t ah[4][4], al[4][4], bh[2][4], bl[2][4];
#pragma unroll
            for (int mi = 0; mi < 4; mi++) {
                uint32_t ad = base + (uint32_t)((aRow + mi * 16) * 80 + (aChk + ks * 2) * 16);
                ldsm4(ah[mi], ad);
                ldsm4(al[mi], ad + FPLANE);
            }
#pragma unroll
            for (int pr = 0; pr < 2; pr++) {
                uint32_t bd = base + 2 * FPLANE +
                              (uint32_t)((wn + pr * 16 + bRowOff) * 80 + (bChk + ks * 2) * 16);
                ldsm4(bh[pr], bd);
                ldsm4(bl[pr], bd + FPLANE);
            }
#pragma unroll
            for (int mi = 0; mi < 4; mi++)
#pragma unroll
                for (int ni = 0; ni < 4; ni++) {
                    const int pr = ni >> 1, o = (ni & 1) * 2;
                    mma16816(acc[mi][ni], ah[mi], bh[pr][o], bh[pr][o + 1]);
                    mma16816(acc[mi][ni], ah[mi], bl[pr][o], bl[pr][o + 1]);
                    mma16816(acc[mi][ni], al[mi], bh[pr][o], bh[pr][o + 1]);
                }
        }
        if (kt + 1 < 32) {
            int nxt = cur ^ 1;
            STS(nxt);
            __syncthreads();
            cur = nxt;
        }
    }

    const int l4 = lane >> 2, l2 = (lane & 3) * 2;
#pragma unroll
    for (int mi = 0; mi < 4; mi++) {
        int r0 = rowBase + wr + mi * 16 + l4;
#pragma unroll
        for (int ni = 0; ni < 4; ni++) {
            int c = colBase + wn + ni * 8 + l2;
            float2 bb = *reinterpret_cast<const float2*>(bias + c);
            *reinterpret_cast<float2*>(C + (size_t)r0 * H_SZ + c) =
                make_float2(tanhf(acc[mi][ni][0] + bb.x), tanhf(acc[mi][ni][1] + bb.y));
            *reinterpret_cast<float2*>(C + (size_t)(r0 + 8) * H_SZ + c) =
                make_float2(tanhf(acc[mi][ni][2] + bb.x), tanhf(acc[mi][ni][3] + bb.y));
        }
    }
}

// =====================================================================
// prep kernels
// =====================================================================

__global__ void __launch_bounds__(256)
conv_wq(const float* __restrict__ W, __nv_bfloat16* __restrict__ Wh,
        uint8_t* __restrict__ qW, uint8_t* __restrict__ qWl, float* __restrict__ sW)
{
    __shared__ float wred[8];
    const int j = blockIdx.x, tid = threadIdx.x, lane = tid & 31, wid = tid >> 5;
    float4 v = *reinterpret_cast<const float4*>(W + (size_t)j * H_SZ + tid * 4);
    float m = fmaxf(fmaxf(fabsf(v.x), fabsf(v.y)), fmaxf(fabsf(v.z), fabsf(v.w)));
#pragma unroll
    for (int o = 16; o > 0; o >>= 1) m = fmaxf(m, __shfl_xor_sync(0xffffffffu, m, o));
    if (lane == 0) wred[wid] = m;
    __syncthreads();
    float mall = wred[0];
#pragma unroll
    for (int i = 1; i < 8; i++) mall = fmaxf(mall, wred[i]);
    float inv = mall > 0.0f ? 127.0f / mall : 0.0f;
    if (tid == 0) sW[j] = mall * (1.0f / 127.0f);

    uint32_t h0, l0, h1, l1;
    bsplit2(v.x, v.y, h0, l0);
    bsplit2(v.z, v.w, h1, l1);
    *reinterpret_cast<uint2*>(Wh + (size_t)j * H_SZ + tid * 4) = make_uint2(h0, h1);
    __nv_bfloat16 bx = __float2bfloat16_rn(v.x), by = __float2bfloat16_rn(v.y);
    __nv_bfloat16 bz = __float2bfloat16_rn(v.z), bw = __float2bfloat16_rn(v.w);
    float lx = v.x - __bfloat162float(bx), ly = v.y - __bfloat162float(by);
    float lz = v.z - __bfloat162float(bz), lw = v.w - __bfloat162float(bw);
    *reinterpret_cast<uint32_t*>(qW  + (size_t)j * H_SZ + tid * 4) = q8x4(v.x, v.y, v.z, v.w, inv);
    *reinterpret_cast<uint32_t*>(qWl + (size_t)j * H_SZ + tid * 4) = q8x4(lx, ly, lz, lw, inv * 256.0f);
}

__global__ void conv_w0t(const float* __restrict__ W0, float* __restrict__ W0T)
{
    int idx = blockIdx.x * blockDim.x + threadIdx.x;
    int d = idx >> 10, k = idx & (H_SZ - 1);
    W0T[idx] = W0[k * 33 + d];
}

// U1 rows: warp-parallel (warp w owns d = w*4..w*4+3), no block barriers in loop
__global__ void __launch_bounds__(256)
prep_u1(const float* __restrict__ h1, const float* __restrict__ W0T,
        __nv_bfloat16* __restrict__ U1h, uint8_t* __restrict__ qU1,
        uint8_t* __restrict__ qU1l, float* __restrict__ sU1)
{
    __shared__ float s1[H_SZ];
    const int b = blockIdx.x, tid = threadIdx.x, lane = tid & 31, w = tid >> 5;
    {
        float4 h = *reinterpret_cast<const float4*>(h1 + (size_t)b * H_SZ + tid * 4);
        s1[tid * 4 + 0] = 1.0f - h.x * h.x;
        s1[tid * 4 + 1] = 1.0f - h.y * h.y;
        s1[tid * 4 + 2] = 1.0f - h.z * h.z;
        s1[tid * 4 + 3] = 1.0f - h.w * h.w;
    }
    __syncthreads();
#pragma unroll 1
    for (int dd = 0; dd < 4; dd++) {
        const int d = w * 4 + dd;
        // pass 1: row max
        float m = 0.0f;
#pragma unroll
        for (int i = 0; i < 8; i++) {
            int k4 = lane + 32 * i;
            float4 wv = *reinterpret_cast<const float4*>(W0T + d * H_SZ + k4 * 4);
            float u0 = s1[k4 * 4 + 0] * wv.x, u1 = s1[k4 * 4 + 1] * wv.y;
            float u2 = s1[k4 * 4 + 2] * wv.z, u3 = s1[k4 * 4 + 3] * wv.w;
            m = fmaxf(m, fmaxf(fmaxf(fabsf(u0), fabsf(u1)), fmaxf(fabsf(u2), fabsf(u3))));
        }
#pragma unroll
        for (int o = 16; o > 0; o >>= 1) m = fmaxf(m, __shfl_xor_sync(0xffffffffu, m, o));
        float inv = m > 0.0f ? 127.0f / m : 0.0f;
        if (lane == 0) sU1[b * 32 + d] = m * (1.0f / 127.0f);
        // pass 2: quantize + bf16 hi
#pragma unroll
        for (int i = 0; i < 8; i++) {
            int k4 = lane + 32 * i;
            float4 wv = *reinterpret_cast<const float4*>(W0T + d * H_SZ + k4 * 4);
            float u0 = s1[k4 * 4 + 0] * wv.x, u1 = s1[k4 * 4 + 1] * wv.y;
            float u2 = s1[k4 * 4 + 2] * wv.z, u3 = s1[k4 * 4 + 3] * wv.w;
            uint32_t h0, l0u, h1b, l1u;
            bsplit2(u0, u1, h0, l0u);
            bsplit2(u2, u3, h1b, l1u);
            __nv_bfloat16 b0 = __float2bfloat16_rn(u0), b1 = __float2bfloat16_rn(u1);
            __nv_bfloat16 b2 = __float2bfloat16_rn(u2), b3 = __float2bfloat16_rn(u3);
            float l0 = u0 - __bfloat162float(b0), l1 = u1 - __bfloat162float(b1);
            float l2 = u2 - __bfloat162float(b2), l3 = u3 - __bfloat162float(b3);
            size_t base = ((size_t)(b * 32 + d) << 10) + k4 * 4;
            *reinterpret_cast<uint2*>(U1h + base) = make_uint2(h0, h1b);
            *reinterpret_cast<uint32_t*>(qU1 + base)  = q8x4(u0, u1, u2, u3, inv);
            *reinterpret_cast<uint32_t*>(qU1l + base) = q8x4(l0, l1, l2, l3, inv * 256.0f);
        }
    }
}

// U2 rows: one warp per row, two-pass, no block barriers
__global__ void __launch_bounds__(256)
quant_u2(const __nv_bfloat16* __restrict__ U2h, const __nv_bfloat16* __restrict__ U2l,
         uint8_t* __restrict__ qU2, uint8_t* __restrict__ qU2l, float* __restrict__ sU2)
{
    const int r = blockIdx.x * 8 + (threadIdx.x >> 5);
    const int lane = threadIdx.x & 31;
    const size_t rb = (size_t)r << 10;
    float m = 0.0f;
#pragma unroll
    for (int i = 0; i < 8; i++) {
        int k4 = lane + 32 * i;
        uint2 hu = *reinterpret_cast<const uint2*>(U2h + rb + k4 * 4);
        uint2 lu = *reinterpret_cast<const uint2*>(U2l + rb + k4 * 4);
        __nv_bfloat162 h01 = *reinterpret_cast<__nv_bfloat162*>(&hu.x);
        __nv_bfloat162 h23 = *reinterpret_cast<__nv_bfloat162*>(&hu.y);
        __nv_bfloat162 l01 = *reinterpret_cast<__nv_bfloat162*>(&lu.x);
        __nv_bfloat162 l23 = *reinterpret_cast<__nv_bfloat162*>(&lu.y);
        float v0 = __bfloat162float(h01.x) + __bfloat162float(l01.x);
        float v1 = __bfloat162float(h01.y) + __bfloat162float(l01.y);
        float v2 = __bfloat162float(h23.x) + __bfloat162float(l23.x);
        float v3 = __bfloat162float(h23.y) + __bfloat162float(l23.y);
        m = fmaxf(m, fmaxf(fmaxf(fabsf(v0), fabsf(v1)), fmaxf(fabsf(v2), fabsf(v3))));
    }
#pragma unroll
    for (int o = 16; o > 0; o >>= 1) m = fmaxf(m, __shfl_xor_sync(0xffffffffu, m, o));
    float inv = m > 0.0f ? 127.0f / m : 0.0f;
    if (lane == 0) sU2[r] = m * (1.0f / 127.0f);
#pragma unroll
    for (int i = 0; i < 8; i++) {
        int k4 = lane + 32 * i;
        uint2 hu = *reinterpret_cast<const uint2*>(U2h + rb + k4 * 4);
        uint2 lu = *reinterpret_cast<const uint2*>(U2l + rb + k4 * 4);
        __nv_bfloat162 h01 = *reinterpret_cast<__nv_bfloat162*>(&hu.x);
        __nv_bfloat162 h23 = *reinterpret_cast<__nv_bfloat162*>(&hu.y);
        __nv_bfloat162 l01 = *reinterpret_cast<__nv_bfloat162*>(&lu.x);
        __nv_bfloat162 l23 = *reinterpret_cast<__nv_bfloat162*>(&lu.y);
        float l0 = __bfloat162float(l01.x), l1 = __bfloat162float(l01.y);
        float l2 = __bfloat162float(l23.x), l3 = __bfloat162float(l23.y);
        float v0 = __bfloat162float(h01.x) + l0, v1 = __bfloat162float(h01.y) + l1;
        float v2 = __bfloat162float(h23.x) + l2, v3 = __bfloat162float(h23.y) + l3;
        *reinterpret_cast<uint32_t*>(qU2 + rb + k4 * 4)  = q8x4(v0, v1, v2, v3, inv);
        *reinterpret_cast<uint32_t*>(qU2l + rb + k4 * 4) = q8x4(l0, l1, l2, l3, inv * 256.0f);
    }
}

__global__ void layer0_kernel(const float* __restrict__ t, const float* __restrict__ z,
                              const float* __restrict__ W0, const float* __restrict__ b0,
                              float* __restrict__ h1)
{
    int idx = blockIdx.x * blockDim.x + threadIdx.x;
    int j = idx & (H_SZ - 1);
    int b = idx >> 10;
    const float* w  = W0 + j * 33;
    const float* zr = z + b * D_SZ;
    float acc = b0[j] + t[0] * w[32];
#pragma unroll
    for (int d = 0; d < 32; d++) acc = fmaf(zr[d], w[d], acc);
    h1[idx] = tanhf(acc);
}

__global__ void __launch_bounds__(256, 4)
out_kernel2(const float* __restrict__ h3, const float* __restrict__ W3,
            const float* __restrict__ b3, float* __restrict__ out)
{
    const int b = blockIdx.x;
    const int wid = threadIdx.x >> 5, lid = threadIdx.x & 31;
    const float* h = h3 + (size_t)b * H_SZ;
#pragma unroll
    for (int dd = 0; dd < 4; dd++) {
        const int d = wid * 4 + dd;
        const float* w = W3 + (size_t)d * H_SZ;
        float acc = 0.0f;
#pragma unroll 4
        for (int k = lid; k < H_SZ; k += 32) acc = fmaf(h[k], w[k], acc);
#pragma unroll
        for (int o = 16; o > 0; o >>= 1) acc += __shfl_xor_sync(0xffffffffu, acc, o);
        if (lid == 0) out[b * D_SZ + d] = acc + b3[d];
    }
}

__global__ void fin_kernel(float* __restrict__ out)
{
    int b = blockIdx.x * blockDim.x + threadIdx.x;
    if (b < B_SZ) {
        float s = 0.0f;
#pragma unroll
        for (int x = 0; x < 8; x++) s += g_tpart[x * B_SZ + b];
        out[B_SZ * D_SZ + b] = -s;
    }
}

// ---------------- launch ----------------
extern "C" void kernel_launch(void* const* d_in, const int* in_sizes, int n_in,
                              void* d_out, int out_size)
{
    const float* t  = (const float*)d_in[0];
    const float* z  = (const float*)d_in[1];
    const float* W0 = (const float*)d_in[2];
    const float* b0 = (const float*)d_in[3];
    const float* W1 = (const float*)d_in[4];
    const float* b1 = (const float*)d_in[5];
    const float* W2 = (const float*)d_in[6];
    const float* b2 = (const float*)d_in[7];
    const float* W3 = (const float*)d_in[8];
    const float* b3 = (const float*)d_in[9];
    float* out = (float*)d_out;

    float *ph1, *ph2, *ph3, *pW0T, *psU1, *psU2, *psW1, *psW2;
    __nv_bfloat16 *pU1h, *pU2h, *pU2l, *pW1h, *pW2h;
    uint8_t *pqU1, *pqU1l, *pqU2, *pqU2l, *pqW1, *pqW1l, *pqW2, *pqW2l;
    cudaGetSymbolAddress((void**)&ph1, g_h1);
    cudaGetSymbolAddress((void**)&ph2, g_h2);
    cudaGetSymbolAddress((void**)&ph3, g_h3);
    cudaGetSymbolAddress((void**)&pW0T, g_W0T);
    cudaGetSymbolAddress((void**)&pU1h, g_U1h);
    cudaGetSymbolAddress((void**)&pU2h, g_U2h);
    cudaGetSymbolAddress((void**)&pU2l, g_U2l);
    cudaGetSymbolAddress((void**)&pqU1, g_qU1);
    cudaGetSymbolAddress((void**)&pqU1l, g_qU1l);
    cudaGetSymbolAddress((void**)&pqU2, g_qU2);
    cudaGetSymbolAddress((void**)&pqU2l, g_qU2l);
    cudaGetSymbolAddress((void**)&pW1h, g_W1h);
    cudaGetSymbolAddress((void**)&pW2h, g_W2h);
    cudaGetSymbolAddress((void**)&pqW1, g_qW1);
    cudaGetSymbolAddress((void**)&pqW1l, g_qW1l);
    cudaGetSymbolAddress((void**)&pqW2, g_qW2);
    cudaGetSymbolAddress((void**)&pqW2l, g_qW2l);
    cudaGetSymbolAddress((void**)&psU1, g_sU1);
    cudaGetSymbolAddress((void**)&psU2, g_sU2);
    cudaGetSymbolAddress((void**)&psW1, g_sW1);
    cudaGetSymbolAddress((void**)&psW2, g_sW2);

    cudaFuncSetAttribute(fwd_gemm, cudaFuncAttributeMaxDynamicSharedMemorySize, SMEM_FWD);
    cudaFuncSetAttribute(tan3<1>,  cudaFuncAttributeMaxDynamicSharedMemorySize, SMEM_TAN);
    cudaFuncSetAttribute(tan3<2>,  cudaFuncAttributeMaxDynamicSharedMemorySize, SMEM_TAN);

    // prep
    layer0_kernel<<<(B_SZ * H_SZ) / 256, 256>>>(t, z, W0, b0, ph1);
    conv_w0t<<<(D_SZ * H_SZ) / 256, 256>>>(W0, pW0T);
    conv_wq<<<H_SZ, 256>>>(W1, pW1h, pqW1, pqW1l, psW1);
    conv_wq<<<H_SZ, 256>>>(W2, pW2h, pqW2, pqW2l, psW2);
    prep_u1<<<B_SZ, 256>>>(ph1, pW0T, pU1h, pqU1, pqU1l, psU1);

    // forward
    dim3 gF(H_SZ / 128, B_SZ / 128);
    fwd_gemm<<<gF, 256, SMEM_FWD>>>(ph1, W1, b1, ph2);
    fwd_gemm<<<gF, 256, SMEM_FWD>>>(ph2, W2, b2, ph3);
    out_kernel2<<<B_SZ, 256>>>(ph3, W3, b3, out);

    // tangent chain: GEMM1 -> quantize U2 -> GEMM2
    dim3 gT(H_SZ / 128, MT / 128);
    tan3<1><<<gT, 256, SMEM_TAN>>>(pU1h, pqU1, pqU1l, psU1, pW1h, pqW1, pqW1l, psW1,
                                   ph2, nullptr, pU2h, pU2l);
    quant_u2<<<MT / 8, 256>>>(pU2h, pU2l, pqU2, pqU2l, psU2);
    tan3<2><<<gT, 256, SMEM_TAN>>>(pU2h, pqU2, pqU2l, psU2, pW2h, pqW2, pqW2l, psW2,
                                   ph3, W3, nullptr, nullptr);

    fin_kernel<<<(B_SZ + 255) / 256, 256>>>(out);
}